// round 5
// baseline (speedup 1.0000x reference)
#include <cuda_runtime.h>
#include <cstdint>

// Distral multi-head tiny MLP (N = 32769 heads), HBM-bound (~120MB streamed once).
// R5: TMA (cp.async.bulk) + mbarrier 3-stage pipeline.
//   - tile = 8 heads (28.8KB of W1|b1|W2), fetched by 3 bulk copies from 1 thread
//   - 8 consumer warps (1 head each) compute from smem while next tiles stream in
//   - producer warp (warp 8) runs the TMA ring; grid-stride over 4097 tiles
// x (N,3) and b2 (N,5) are tiny (~1MB) -> scalar LDG by consumers (keeps TMA
// chunk sizes 16B-multiples even on the ragged last tile).

#define HID 100
#define OUT 5
#define HPT 8                       // heads per tile
#define STAGES 3
#define W1_F (HPT * HID * 3)        // 2400 floats
#define B1_F (HPT * HID)            //  800
#define W2_F (HPT * OUT * HID)      // 4000
#define TILE_F (W1_F + B1_F + W2_F) // 7200 floats = 28800 B
#define HEAD_BYTES 3600             // (300+100+500)*4 per head
#define THREADS 288                 // 8 consumer warps + 1 producer warp

__device__ __forceinline__ uint32_t s2u(const void* p) {
    uint32_t a;
    asm("{ .reg .u64 t; cvta.to.shared.u64 t, %1; cvt.u32.u64 %0, t; }"
        : "=r"(a) : "l"(p));
    return a;
}

__device__ __forceinline__ void mbar_init(uint32_t m, uint32_t cnt) {
    asm volatile("mbarrier.init.shared.b64 [%0], %1;" :: "r"(m), "r"(cnt) : "memory");
}
__device__ __forceinline__ void mbar_expect_tx(uint32_t m, uint32_t bytes) {
    asm volatile("mbarrier.arrive.expect_tx.shared.b64 _, [%0], %1;"
                 :: "r"(m), "r"(bytes) : "memory");
}
__device__ __forceinline__ void mbar_arrive(uint32_t m) {
    asm volatile("mbarrier.arrive.shared.b64 _, [%0];" :: "r"(m) : "memory");
}
__device__ __forceinline__ void mbar_wait(uint32_t m, uint32_t phase) {
    asm volatile(
        "{\n\t.reg .pred P;\n\t"
        "WL_%=:\n\t"
        "mbarrier.try_wait.parity.acquire.cta.shared::cta.b64 P, [%0], %1, 0x989680;\n\t"
        "@P bra.uni WD_%=;\n\t"
        "bra.uni WL_%=;\n\t"
        "WD_%=:\n\t}"
        :: "r"(m), "r"(phase) : "memory");
}
__device__ __forceinline__ void bulk_g2s(uint32_t dst, const void* src,
                                         uint32_t bytes, uint32_t m) {
    asm volatile(
        "cp.async.bulk.shared::cta.global.mbarrier::complete_tx::bytes [%0], [%1], %2, [%3];"
        :: "r"(dst), "l"(src), "r"(bytes), "r"(m) : "memory");
}

__global__ __launch_bounds__(THREADS) void distral_kernel(
    const float* __restrict__ x,
    const float* __restrict__ W1,
    const float* __restrict__ b1,
    const float* __restrict__ W2,
    const float* __restrict__ b2,
    float* __restrict__ out,
    int n_heads, int n_tiles)
{
    extern __shared__ __align__(16) float dsm[];          // STAGES * TILE_F
    __shared__ __align__(8) uint64_t s_full [STAGES];
    __shared__ __align__(8) uint64_t s_empty[STAGES];

    const int tid  = threadIdx.x;
    const int wid  = tid >> 5;
    const int lane = tid & 31;

    uint32_t full_b  = s2u(s_full);
    uint32_t empty_b = s2u(s_empty);

    if (tid == 0) {
        #pragma unroll
        for (int s = 0; s < STAGES; s++) {
            mbar_init(full_b  + s * 8, 1);   // producer's expect_tx arrival
            mbar_init(empty_b + s * 8, 8);   // one arrive per consumer warp
        }
    }
    __syncthreads();

    if (wid == 8) {
        // ================= producer (single thread of warp 8) =================
        if (lane == 0) {
            int stage = 0, phase = 1;        // phase=1: first empty-wait passes
            for (int t = blockIdx.x; t < n_tiles; t += gridDim.x) {
                const int h0 = t * HPT;
                const uint32_t h = (uint32_t)min(HPT, n_heads - h0);

                mbar_wait(empty_b + stage * 8, phase);

                uint32_t base = s2u(dsm + stage * TILE_F);
                uint32_t mb   = full_b + stage * 8;
                mbar_expect_tx(mb, h * HEAD_BYTES);
                bulk_g2s(base,             W1 + (size_t)h0 * (HID * 3), h * (HID * 3 * 4), mb);
                bulk_g2s(base + W1_F * 4,  b1 + (size_t)h0 * HID,       h * (HID * 4),     mb);
                bulk_g2s(base + (W1_F + B1_F) * 4,
                                           W2 + (size_t)h0 * (OUT * HID), h * (OUT * HID * 4), mb);

                if (++stage == STAGES) { stage = 0; phase ^= 1; }
            }
        }
    } else {
        // ======================= consumers (warps 0..7) =======================
        int stage = 0, phase = 0;
        for (int t = blockIdx.x; t < n_tiles; t += gridDim.x) {
            const int head = t * HPT + wid;

            mbar_wait(full_b + stage * 8, phase);

            if (head < n_heads) {
                const float* sw1 = dsm + stage * TILE_F + wid * (HID * 3);
                const float* sb1 = dsm + stage * TILE_F + W1_F + wid * HID;
                const float* sw2 = dsm + stage * TILE_F + W1_F + B1_F + wid * (OUT * HID);

                const float x0 = __ldg(x + (size_t)head * 3 + 0);
                const float x1 = __ldg(x + (size_t)head * 3 + 1);
                const float x2 = __ldg(x + (size_t)head * 3 + 2);

                // hidden: lane owns j = lane + 32m (stride-3 smem, conflict-free)
                float h[4];
                #pragma unroll
                for (int m = 0; m < 4; m++) {
                    int j = lane + 32 * m;
                    if (j < HID) {
                        float v = fmaf(sw1[j * 3 + 0], x0,
                                  fmaf(sw1[j * 3 + 1], x1,
                                  fmaf(sw1[j * 3 + 2], x2, sb1[j])));
                        h[m] = fmaxf(v, 0.0f);
                    } else {
                        h[m] = 0.0f;
                    }
                }

                float logits[OUT];
                #pragma unroll
                for (int o = 0; o < OUT; o++) {
                    float p = 0.0f;
                    #pragma unroll
                    for (int m = 0; m < 4; m++) {
                        int j = lane + 32 * m;
                        if (j < HID) p = fmaf(sw2[o * HID + j], h[m], p);
                    }
                    #pragma unroll
                    for (int s = 16; s; s >>= 1)
                        p += __shfl_xor_sync(0xffffffffu, p, s);
                    logits[o] = p + __ldg(b2 + (size_t)head * OUT + o);
                }

                float mx = logits[0];
                #pragma unroll
                for (int o = 1; o < OUT; o++) mx = fmaxf(mx, logits[o]);
                float e[OUT], sum = 0.0f;
                #pragma unroll
                for (int o = 0; o < OUT; o++) { e[o] = __expf(logits[o] - mx); sum += e[o]; }
                float inv = __frcp_rn(sum);

                if (lane < OUT)
                    out[(size_t)head * OUT + lane] = e[lane] * inv;
            }

            __syncwarp();
            if (lane == 0) mbar_arrive(empty_b + stage * 8);

            if (++stage == STAGES) { stage = 0; phase ^= 1; }
        }
    }
}

extern "C" void kernel_launch(void* const* d_in, const int* in_sizes, int n_in,
                              void* d_out, int out_size)
{
    const float* x  = (const float*)d_in[0];
    const float* W1 = (const float*)d_in[1];
    const float* b1 = (const float*)d_in[2];
    const float* W2 = (const float*)d_in[3];
    const float* b2 = (const float*)d_in[4];
    float* out = (float*)d_out;

    const int n_heads = in_sizes[0] / 3;             // x is (N, 3)
    const int n_tiles = (n_heads + HPT - 1) / HPT;   // 4097

    const int smem_bytes = STAGES * TILE_F * 4;      // 86400
    static bool attr_set = false;
    cudaFuncSetAttribute(distral_kernel,
                         cudaFuncAttributeMaxDynamicSharedMemorySize, smem_bytes);
    (void)attr_set;

    int blocks = 304;                                // ~2 per SM, grid-stride
    if (blocks > n_tiles) blocks = n_tiles;

    distral_kernel<<<blocks, THREADS, smem_bytes>>>(x, W1, b1, W2, b2, out,
                                                    n_heads, n_tiles);
}

// round 6
// speedup vs baseline: 1.1631x; 1.1631x over previous
#include <cuda_runtime.h>
#include <cstdint>

// Distral multi-head tiny MLP (N = 32769 heads), HBM-bound (~120MB streamed once).
// R6: chunk-per-lane ownership so ALL weights load as float4 (9 LDG.128/head),
// plus explicit ping-pong software pipeline (load head t+stride while computing
// head t) in a warp-strided persistent loop. No smem, no barriers.
//   lane l (l<25) owns hidden units j in [4l, 4l+4):
//     W1 floats [12l,12l+12) = 3 float4;  b1 [4l,4l+4) = 1 float4;
//     W2 row o floats [100o+4l, +4) = float4 idx 25o+l.

#define HID 100
#define OUT 5

struct Stage {
    float4 w1[3];
    float4 b1v;
    float4 w2[OUT];
    float  x0, x1, x2;
    float  bo[OUT];
};

__device__ __forceinline__ void load_stage(
    Stage& s, int head, int lane,
    const float* __restrict__ W1, const float* __restrict__ b1,
    const float* __restrict__ W2, const float* __restrict__ x,
    const float* __restrict__ b2)
{
    const float4* g1 = (const float4*)(W1 + (size_t)head * (HID * 3));
    const float4* gb = (const float4*)(b1 + (size_t)head * HID);
    const float4* g2 = (const float4*)(W2 + (size_t)head * (OUT * HID));

    if (lane < 25) {
        s.w1[0] = __ldg(g1 + 3 * lane + 0);
        s.w1[1] = __ldg(g1 + 3 * lane + 1);
        s.w1[2] = __ldg(g1 + 3 * lane + 2);
        s.b1v   = __ldg(gb + lane);
        #pragma unroll
        for (int o = 0; o < OUT; o++) s.w2[o] = __ldg(g2 + 25 * o + lane);
    }
    s.x0 = __ldg(x + (size_t)head * 3 + 0);
    s.x1 = __ldg(x + (size_t)head * 3 + 1);
    s.x2 = __ldg(x + (size_t)head * 3 + 2);
    #pragma unroll
    for (int o = 0; o < OUT; o++) s.bo[o] = __ldg(b2 + (size_t)head * OUT + o);
}

__device__ __forceinline__ void compute_store(
    const Stage& s, int head, int lane, float* __restrict__ out)
{
    const float f[12] = { s.w1[0].x, s.w1[0].y, s.w1[0].z, s.w1[0].w,
                          s.w1[1].x, s.w1[1].y, s.w1[1].z, s.w1[1].w,
                          s.w1[2].x, s.w1[2].y, s.w1[2].z, s.w1[2].w };
    const float bb[4] = { s.b1v.x, s.b1v.y, s.b1v.z, s.b1v.w };

    float h[4];
    #pragma unroll
    for (int k = 0; k < 4; k++) {
        float v = fmaf(f[3 * k + 0], s.x0,
                  fmaf(f[3 * k + 1], s.x1,
                  fmaf(f[3 * k + 2], s.x2, bb[k])));
        h[k] = fmaxf(v, 0.0f);
    }

    float logits[OUT];
    #pragma unroll
    for (int o = 0; o < OUT; o++) {
        float4 q = s.w2[o];
        float p = fmaf(q.x, h[0], fmaf(q.y, h[1], fmaf(q.z, h[2], q.w * h[3])));
        if (lane >= 25) p = 0.0f;   // inactive lanes contribute zero
        #pragma unroll
        for (int sft = 16; sft; sft >>= 1)
            p += __shfl_xor_sync(0xffffffffu, p, sft);
        logits[o] = p + s.bo[o];
    }

    float mx = logits[0];
    #pragma unroll
    for (int o = 1; o < OUT; o++) mx = fmaxf(mx, logits[o]);
    float e[OUT], sum = 0.0f;
    #pragma unroll
    for (int o = 0; o < OUT; o++) { e[o] = __expf(logits[o] - mx); sum += e[o]; }
    float inv = __frcp_rn(sum);

    if (lane < OUT)
        out[(size_t)head * OUT + lane] = e[lane] * inv;
}

__global__ __launch_bounds__(128) void distral_kernel(
    const float* __restrict__ x,
    const float* __restrict__ W1,
    const float* __restrict__ b1,
    const float* __restrict__ W2,
    const float* __restrict__ b2,
    float* __restrict__ out,
    int n_heads)
{
    const int lane  = threadIdx.x & 31;
    const int gwarp = (blockIdx.x * blockDim.x + threadIdx.x) >> 5;
    const int total = (gridDim.x * blockDim.x) >> 5;

    int t = gwarp;
    if (t >= n_heads) return;

    Stage s0, s1;
    load_stage(s0, t, lane, W1, b1, W2, x, b2);

    for (;;) {
        int tn = t + total;
        // stage A: prefetch tn into s1, compute s0
        if (tn < n_heads) {
            load_stage(s1, tn, lane, W1, b1, W2, x, b2);
            compute_store(s0, t, lane, out);
        } else {
            compute_store(s0, t, lane, out);
            break;
        }
        t = tn;

        tn = t + total;
        // stage B: prefetch tn into s0, compute s1
        if (tn < n_heads) {
            load_stage(s0, tn, lane, W1, b1, W2, x, b2);
            compute_store(s1, t, lane, out);
        } else {
            compute_store(s1, t, lane, out);
            break;
        }
        t = tn;
    }
}

extern "C" void kernel_launch(void* const* d_in, const int* in_sizes, int n_in,
                              void* d_out, int out_size)
{
    const float* x  = (const float*)d_in[0];
    const float* W1 = (const float*)d_in[1];
    const float* b1 = (const float*)d_in[2];
    const float* W2 = (const float*)d_in[3];
    const float* b2 = (const float*)d_in[4];
    float* out = (float*)d_out;

    const int n_heads = in_sizes[0] / 3;   // x is (N, 3)

    // ~4096 warps, each streams ~8 heads through the 2-stage pipeline
    const int threads = 128;               // 4 warps/block
    const int blocks  = 1024;

    distral_kernel<<<blocks, threads>>>(x, W1, b1, W2, b2, out, n_heads);
}

// round 8
// speedup vs baseline: 1.1948x; 1.0273x over previous
#include <cuda_runtime.h>
#include <cstdint>

// Distral multi-head tiny MLP (N = 32769 heads). All load structures pin at
// ~5.2 TB/s DRAM; R8 targets L2 residency across graph replays instead:
// weights (119MB) < L2 (126MB), L2 survives launches. Weight loads carry an
// L2::evict_last cache-hint policy (createpolicy + ld.global.nc.L2::cache_hint,
// the form sm_103a ptxas accepts for .f32/.v4.f32). float4 chunk-per-lane
// ownership (9 wide loads/head), grid-strided, no smem/barriers.

#define HID 100
#define OUT 5

__device__ __forceinline__ uint64_t mk_policy() {
    uint64_t p;
    asm("createpolicy.fractional.L2::evict_last.b64 %0, 1.0;" : "=l"(p));
    return p;
}
__device__ __forceinline__ float4 ldg_el(const float4* p, uint64_t pol) {
    float4 v;
    asm volatile("ld.global.nc.L2::cache_hint.v4.f32 {%0,%1,%2,%3}, [%4], %5;"
                 : "=f"(v.x), "=f"(v.y), "=f"(v.z), "=f"(v.w)
                 : "l"(p), "l"(pol));
    return v;
}
__device__ __forceinline__ float ldg_el_f(const float* p, uint64_t pol) {
    float v;
    asm volatile("ld.global.nc.L2::cache_hint.f32 %0, [%1], %2;"
                 : "=f"(v) : "l"(p), "l"(pol));
    return v;
}

__global__ __launch_bounds__(256) void distral_kernel(
    const float* __restrict__ x,
    const float* __restrict__ W1,
    const float* __restrict__ b1,
    const float* __restrict__ W2,
    const float* __restrict__ b2,
    float* __restrict__ out,
    int n_heads)
{
    const int lane  = threadIdx.x & 31;
    const int gwarp = (blockIdx.x * blockDim.x + threadIdx.x) >> 5;
    const int nwarp = (gridDim.x * blockDim.x) >> 5;

    const uint64_t pol = mk_policy();

    // lane l (l<25) owns hidden units j in [4l, 4l+4)
    for (int head = gwarp; head < n_heads; head += nwarp) {
        const float4* g1 = (const float4*)(W1 + (size_t)head * (HID * 3));
        const float4* gb = (const float4*)(b1 + (size_t)head * HID);
        const float4* g2 = (const float4*)(W2 + (size_t)head * (OUT * HID));

        float4 w1a, w1b, w1c, b1v, w2v[OUT];
        if (lane < 25) {
            w1a = ldg_el(g1 + 3 * lane + 0, pol);
            w1b = ldg_el(g1 + 3 * lane + 1, pol);
            w1c = ldg_el(g1 + 3 * lane + 2, pol);
            b1v = ldg_el(gb + lane, pol);
            #pragma unroll
            for (int o = 0; o < OUT; o++) w2v[o] = ldg_el(g2 + 25 * o + lane, pol);
        } else {
            w1a = w1b = w1c = b1v = make_float4(0.f, 0.f, 0.f, 0.f);
            #pragma unroll
            for (int o = 0; o < OUT; o++) w2v[o] = make_float4(0.f, 0.f, 0.f, 0.f);
        }

        const float x0 = ldg_el_f(x + (size_t)head * 3 + 0, pol);
        const float x1 = ldg_el_f(x + (size_t)head * 3 + 1, pol);
        const float x2 = ldg_el_f(x + (size_t)head * 3 + 2, pol);

        const float f[12] = { w1a.x, w1a.y, w1a.z, w1a.w,
                              w1b.x, w1b.y, w1b.z, w1b.w,
                              w1c.x, w1c.y, w1c.z, w1c.w };
        const float bb[4] = { b1v.x, b1v.y, b1v.z, b1v.w };

        float h[4];
        #pragma unroll
        for (int k = 0; k < 4; k++) {
            float v = fmaf(f[3 * k + 0], x0,
                      fmaf(f[3 * k + 1], x1,
                      fmaf(f[3 * k + 2], x2, bb[k])));
            h[k] = fmaxf(v, 0.0f);
        }

        float logits[OUT];
        #pragma unroll
        for (int o = 0; o < OUT; o++) {
            float4 q = w2v[o];
            float p = fmaf(q.x, h[0], fmaf(q.y, h[1], fmaf(q.z, h[2], q.w * h[3])));
            #pragma unroll
            for (int s = 16; s; s >>= 1)
                p += __shfl_xor_sync(0xffffffffu, p, s);
            logits[o] = p + ldg_el_f(b2 + (size_t)head * OUT + o, pol);
        }

        float mx = logits[0];
        #pragma unroll
        for (int o = 1; o < OUT; o++) mx = fmaxf(mx, logits[o]);
        float e[OUT], sum = 0.0f;
        #pragma unroll
        for (int o = 0; o < OUT; o++) { e[o] = __expf(logits[o] - mx); sum += e[o]; }
        float inv = __frcp_rn(sum);

        if (lane < OUT)
            out[(size_t)head * OUT + lane] = e[lane] * inv;
    }
}

extern "C" void kernel_launch(void* const* d_in, const int* in_sizes, int n_in,
                              void* d_out, int out_size)
{
    const float* x  = (const float*)d_in[0];
    const float* W1 = (const float*)d_in[1];
    const float* b1 = (const float*)d_in[2];
    const float* W2 = (const float*)d_in[3];
    const float* b2 = (const float*)d_in[4];
    float* out = (float*)d_out;

    const int n_heads = in_sizes[0] / 3;   // x is (N, 3)

    const int blocks = 148 * 4;            // 8 warps/block, ~single co-resident wave
    distral_kernel<<<blocks, 256>>>(x, W1, b1, W2, b2, out, n_heads);
}

// round 9
// speedup vs baseline: 1.7391x; 1.4556x over previous
#include <cuda_runtime.h>
#include <cstdint>

// Distral multi-head tiny MLP (N = 32769 heads). ~120MB read once per launch;
// all load structures pin DRAM at ~5.2 TB/s. R9: exploit L2 persistence across
// graph replays with PARTIAL protection (R8's full-footprint evict_last self-
// thrashed): W1+b1 (52.4MB, 42% of 126MB L2) -> evict_last; W2 (66MB stream)
// -> evict_first so it can't displace the protected set. float4 chunk-per-lane
// ownership, grid-strided, no smem/barriers.

#define HID 100
#define OUT 5

__device__ __forceinline__ uint64_t pol_keep() {
    uint64_t p;
    asm("createpolicy.fractional.L2::evict_last.b64 %0, 1.0;" : "=l"(p));
    return p;
}
__device__ __forceinline__ uint64_t pol_stream() {
    uint64_t p;
    asm("createpolicy.fractional.L2::evict_first.b64 %0, 1.0;" : "=l"(p));
    return p;
}
__device__ __forceinline__ float4 ldg_hint(const float4* p, uint64_t pol) {
    float4 v;
    asm volatile("ld.global.nc.L2::cache_hint.v4.f32 {%0,%1,%2,%3}, [%4], %5;"
                 : "=f"(v.x), "=f"(v.y), "=f"(v.z), "=f"(v.w)
                 : "l"(p), "l"(pol));
    return v;
}

__global__ __launch_bounds__(256) void distral_kernel(
    const float* __restrict__ x,
    const float* __restrict__ W1,
    const float* __restrict__ b1,
    const float* __restrict__ W2,
    const float* __restrict__ b2,
    float* __restrict__ out,
    int n_heads)
{
    const int lane  = threadIdx.x & 31;
    const int gwarp = (blockIdx.x * blockDim.x + threadIdx.x) >> 5;
    const int nwarp = (gridDim.x * blockDim.x) >> 5;

    const uint64_t pk = pol_keep();    // W1, b1: resident set (52.4MB)
    const uint64_t ps = pol_stream();  // W2: streaming set (65.5MB)

    // lane l (l<25) owns hidden units j in [4l, 4l+4)
    for (int head = gwarp; head < n_heads; head += nwarp) {
        const float4* g1 = (const float4*)(W1 + (size_t)head * (HID * 3));
        const float4* gb = (const float4*)(b1 + (size_t)head * HID);
        const float4* g2 = (const float4*)(W2 + (size_t)head * (OUT * HID));

        float4 w1a, w1b, w1c, b1v, w2v[OUT];
        if (lane < 25) {
            w1a = ldg_hint(g1 + 3 * lane + 0, pk);
            w1b = ldg_hint(g1 + 3 * lane + 1, pk);
            w1c = ldg_hint(g1 + 3 * lane + 2, pk);
            b1v = ldg_hint(gb + lane, pk);
            #pragma unroll
            for (int o = 0; o < OUT; o++) w2v[o] = ldg_hint(g2 + 25 * o + lane, ps);
        } else {
            w1a = w1b = w1c = b1v = make_float4(0.f, 0.f, 0.f, 0.f);
            #pragma unroll
            for (int o = 0; o < OUT; o++) w2v[o] = make_float4(0.f, 0.f, 0.f, 0.f);
        }

        const float x0 = __ldg(x + (size_t)head * 3 + 0);
        const float x1 = __ldg(x + (size_t)head * 3 + 1);
        const float x2 = __ldg(x + (size_t)head * 3 + 2);

        const float f[12] = { w1a.x, w1a.y, w1a.z, w1a.w,
                              w1b.x, w1b.y, w1b.z, w1b.w,
                              w1c.x, w1c.y, w1c.z, w1c.w };
        const float bb[4] = { b1v.x, b1v.y, b1v.z, b1v.w };

        float h[4];
        #pragma unroll
        for (int k = 0; k < 4; k++) {
            float v = fmaf(f[3 * k + 0], x0,
                      fmaf(f[3 * k + 1], x1,
                      fmaf(f[3 * k + 2], x2, bb[k])));
            h[k] = fmaxf(v, 0.0f);
        }

        float logits[OUT];
        #pragma unroll
        for (int o = 0; o < OUT; o++) {
            float4 q = w2v[o];
            float p = fmaf(q.x, h[0], fmaf(q.y, h[1], fmaf(q.z, h[2], q.w * h[3])));
            #pragma unroll
            for (int s = 16; s; s >>= 1)
                p += __shfl_xor_sync(0xffffffffu, p, s);
            logits[o] = p + __ldg(b2 + (size_t)head * OUT + o);
        }

        float mx = logits[0];
        #pragma unroll
        for (int o = 1; o < OUT; o++) mx = fmaxf(mx, logits[o]);
        float e[OUT], sum = 0.0f;
        #pragma unroll
        for (int o = 0; o < OUT; o++) { e[o] = __expf(logits[o] - mx); sum += e[o]; }
        float inv = __frcp_rn(sum);

        if (lane < OUT)
            out[(size_t)head * OUT + lane] = e[lane] * inv;
    }
}

extern "C" void kernel_launch(void* const* d_in, const int* in_sizes, int n_in,
                              void* d_out, int out_size)
{
    const float* x  = (const float*)d_in[0];
    const float* W1 = (const float*)d_in[1];
    const float* b1 = (const float*)d_in[2];
    const float* W2 = (const float*)d_in[3];
    const float* b2 = (const float*)d_in[4];
    float* out = (float*)d_out;

    const int n_heads = in_sizes[0] / 3;   // x is (N, 3)

    const int blocks = 148 * 6;            // more warps: L2-hit regime is latency-bound
    distral_kernel<<<blocks, 256>>>(x, W1, b1, W2, b2, out, n_heads);
}